// round 1
// baseline (speedup 1.0000x reference)
#include <cuda_runtime.h>
#include <cuda_bf16.h>
#include <math.h>

// Problem constants
#define B     2
#define S     4096
#define E     1024
#define H     16
#define D     64
#define WIN   256
#define M_ROWS (B * S)        // 8192

// Scratch buffers (device globals: allocation-free rule)
__device__ float g_q[B * H * S * D];    // [b,h,s,d]
__device__ float g_k[B * H * S * D];
__device__ float g_v[B * H * S * D];
__device__ float g_ctx[B * S * E];      // [b,s,e] row-major

// ---------------------------------------------------------------------------
// SIMT fp32 GEMM:  C[n,o] = sum_k A[n,k] * Wt[o,k] + bias[o]
// A: [M,K] row-major, Wt: [N,K] row-major (i.e. computes A @ Wt^T).
// mode 0: C row-major [M,N].
// mode 1: C scattered to [b,h,s,d] layout (n = b*S+sr, o = hh*64+dd).
// Block tile 128x128, K-step 16, 256 threads, 8x8 per thread.
// All dims are exact multiples, no bounds checks needed.
// ---------------------------------------------------------------------------
__global__ void __launch_bounds__(256, 2)
sgemm_nt(const float* __restrict__ A, const float* __restrict__ Wt,
         const float* __restrict__ bias, float* __restrict__ C,
         int M, int N, int K, int mode)
{
    __shared__ float As[16][128];
    __shared__ float Bs[16][128];

    const int tid = threadIdx.x;
    const int tx  = tid & 15;          // 0..15  (N direction)
    const int ty  = tid >> 4;          // 0..15  (M direction)
    const int m0  = blockIdx.y * 128;
    const int n0  = blockIdx.x * 128;

    // global->smem loading pattern: 2 threads per row, 8 floats each
    const int lrow = tid >> 1;         // 0..127
    const int lcol = (tid & 1) * 8;    // 0 or 8

    float acc[8][8];
    #pragma unroll
    for (int i = 0; i < 8; i++)
        #pragma unroll
        for (int j = 0; j < 8; j++) acc[i][j] = 0.f;

    const float* Arow = A  + (size_t)(m0 + lrow) * K + lcol;
    const float* Brow = Wt + (size_t)(n0 + lrow) * K + lcol;

    for (int k0 = 0; k0 < K; k0 += 16) {
        __syncthreads();
        float4 a0 = *(const float4*)(Arow + k0);
        float4 a1 = *(const float4*)(Arow + k0 + 4);
        float4 b0 = *(const float4*)(Brow + k0);
        float4 b1 = *(const float4*)(Brow + k0 + 4);
        As[lcol + 0][lrow] = a0.x; As[lcol + 1][lrow] = a0.y;
        As[lcol + 2][lrow] = a0.z; As[lcol + 3][lrow] = a0.w;
        As[lcol + 4][lrow] = a1.x; As[lcol + 5][lrow] = a1.y;
        As[lcol + 6][lrow] = a1.z; As[lcol + 7][lrow] = a1.w;
        Bs[lcol + 0][lrow] = b0.x; Bs[lcol + 1][lrow] = b0.y;
        Bs[lcol + 2][lrow] = b0.z; Bs[lcol + 3][lrow] = b0.w;
        Bs[lcol + 4][lrow] = b1.x; Bs[lcol + 5][lrow] = b1.y;
        Bs[lcol + 6][lrow] = b1.z; Bs[lcol + 7][lrow] = b1.w;
        __syncthreads();

        #pragma unroll
        for (int kk = 0; kk < 16; kk++) {
            float a[8], b[8];
            *(float4*)(a)     = *(const float4*)&As[kk][ty * 8];
            *(float4*)(a + 4) = *(const float4*)&As[kk][ty * 8 + 4];
            *(float4*)(b)     = *(const float4*)&Bs[kk][tx * 8];
            *(float4*)(b + 4) = *(const float4*)&Bs[kk][tx * 8 + 4];
            #pragma unroll
            for (int i = 0; i < 8; i++)
                #pragma unroll
                for (int j = 0; j < 8; j++)
                    acc[i][j] = fmaf(a[i], b[j], acc[i][j]);
        }
    }

    // epilogue
    #pragma unroll
    for (int i = 0; i < 8; i++) {
        int n = m0 + ty * 8 + i;
        #pragma unroll
        for (int j = 0; j < 8; j++) {
            int o = n0 + tx * 8 + j;
            float val = acc[i][j] + bias[o];
            if (mode == 0) {
                C[(size_t)n * N + o] = val;
            } else {
                int bb = n >> 12;          // n / 4096
                int sr = n & 4095;
                int hh = o >> 6;
                int dd = o & 63;
                C[(((size_t)((bb << 4) + hh) << 12) + sr) * 64 + dd] = val;
            }
        }
    }
}

// ---------------------------------------------------------------------------
// "RoPE": rotation angle depends on HEAD INDEX only (per the reference).
// buf layout [b,h,s,d]; element pair (2i, 2i+1).
// ang(j) = head * 10000^(-(j mod 32)/32)
// out[2i]   = x[2i]*cos(ang(2i))   - x[2i+1]*sin(ang(2i))
// out[2i+1] = x[2i+1]*cos(ang(2i+1)) + x[2i]*sin(ang(2i+1))
// then multiply by `scale` (1/sqrt(d) for q, 1 for k).
// ---------------------------------------------------------------------------
__global__ void rope_kernel(float* __restrict__ buf, float scale)
{
    const int NP = B * H * S * (D / 2);   // pair count
    int idx = blockIdx.x * blockDim.x + threadIdx.x;
    if (idx >= NP) return;

    int i  = idx & 31;                    // pair within head-dim
    int bh = idx >> 17;                   // / (4096*32)
    int hh = bh & 15;

    int j0 = 2 * i;
    int m0 = j0 & 31;
    int m1 = (j0 + 1) & 31;
    const float L = 13.2877123795494f / 32.0f;   // log2(10000)/32
    float f0 = exp2f(-(float)m0 * L);
    float f1 = exp2f(-(float)m1 * L);
    float a0 = (float)hh * f0;
    float a1 = (float)hh * f1;
    float s0, c0, s1, c1;
    sincosf(a0, &s0, &c0);
    sincosf(a1, &s1, &c1);

    float x0 = buf[2 * idx];
    float x1 = buf[2 * idx + 1];
    buf[2 * idx]     = (x0 * c0 - x1 * s0) * scale;
    buf[2 * idx + 1] = (x1 * c1 + x0 * s1) * scale;
}

// ---------------------------------------------------------------------------
// Sliding-window attention, flash-style online softmax.
// Mask reduces to |kpos - qpos| <= WIN (and 0<=kpos<S).
// grid = (S/128, B*H); block = 128 threads; 1 query per thread.
// Key range per q-block: [qstart-256, qstart+383] = 640 keys = 10 tiles of 64.
// Writes context to g_ctx in [b,s,e] row-major.
// ---------------------------------------------------------------------------
__global__ void __launch_bounds__(128)
attn_kernel()
{
    __shared__ float Ks[64][64];   // 16 KB
    __shared__ float Vs[64][64];   // 16 KB

    const int qb  = blockIdx.x;          // 0..31
    const int bh  = blockIdx.y;          // 0..31
    const int t   = threadIdx.x;         // 0..127
    const int qpos = qb * 128 + t;

    const float* qbase = g_q + (size_t)bh * S * D;
    const float* kbase = g_k + (size_t)bh * S * D;
    const float* vbase = g_v + (size_t)bh * S * D;

    // load my query row into registers
    float q[64];
    {
        const float4* qp = (const float4*)(qbase + (size_t)qpos * D);
        #pragma unroll
        for (int c = 0; c < 16; c++) {
            float4 v4 = qp[c];
            q[4 * c + 0] = v4.x; q[4 * c + 1] = v4.y;
            q[4 * c + 2] = v4.z; q[4 * c + 3] = v4.w;
        }
    }

    float acc[64];
    #pragma unroll
    for (int c = 0; c < 64; c++) acc[c] = 0.f;
    float m = -3.0e38f, l = 0.f;

    const int lrow = t >> 1;        // 0..63
    const int lhalf = (t & 1) * 8;  // float4 offset: 0 or 8 (32 floats each)

    int k0 = qb * 128 - 2 * WIN / 2 - 128;   // qstart - 256 ... computed below
    k0 = qb * 128 - 256;

    for (int kt = 0; kt < 10; kt++, k0 += 64) {
        __syncthreads();
        // load 64-key K/V tiles; zero-fill out-of-range rows
        {
            int kr = k0 + lrow;
            bool ok = (kr >= 0) && (kr < S);
            const float4* kp = (const float4*)(kbase + (size_t)(ok ? kr : 0) * D);
            const float4* vp = (const float4*)(vbase + (size_t)(ok ? kr : 0) * D);
            float4 z4 = make_float4(0.f, 0.f, 0.f, 0.f);
            #pragma unroll
            for (int c = 0; c < 8; c++) {
                float4 kv = ok ? kp[lhalf + c] : z4;
                float4 vv = ok ? vp[lhalf + c] : z4;
                *(float4*)&Ks[lrow][(lhalf + c) * 4] = kv;
                *(float4*)&Vs[lrow][(lhalf + c) * 4] = vv;
            }
        }
        __syncthreads();

        // process 64 keys in batches of 8
        for (int jb = 0; jb < 64; jb += 8) {
            float sc[8];
            #pragma unroll
            for (int jj = 0; jj < 8; jj++) {
                int j = jb + jj;
                const float4* kr4 = (const float4*)Ks[j];
                float s = 0.f;
                #pragma unroll
                for (int c = 0; c < 16; c++) {
                    float4 kv = kr4[c];
                    s = fmaf(q[4 * c + 0], kv.x, s);
                    s = fmaf(q[4 * c + 1], kv.y, s);
                    s = fmaf(q[4 * c + 2], kv.z, s);
                    s = fmaf(q[4 * c + 3], kv.w, s);
                }
                int kp = k0 + j;
                int dlt = kp - qpos;
                bool valid = (dlt >= -WIN) && (dlt <= WIN) && (kp >= 0) && (kp < S);
                sc[jj] = valid ? s : -3.0e38f;
            }
            float bm = sc[0];
            #pragma unroll
            for (int jj = 1; jj < 8; jj++) bm = fmaxf(bm, sc[jj]);
            if (bm < -1.0e37f) continue;    // whole batch masked

            float mnew  = fmaxf(m, bm);
            float scale = __expf(m - mnew); // m=-3e38 first time -> 0
            float p[8];
            float ps = 0.f;
            #pragma unroll
            for (int jj = 0; jj < 8; jj++) {
                p[jj] = (sc[jj] > -1.0e37f) ? __expf(sc[jj] - mnew) : 0.f;
                ps += p[jj];
            }
            l = l * scale + ps;
            m = mnew;
            #pragma unroll
            for (int c = 0; c < 64; c++) acc[c] *= scale;
            #pragma unroll
            for (int jj = 0; jj < 8; jj++) {
                float pj = p[jj];
                const float4* vr = (const float4*)Vs[jb + jj];
                #pragma unroll
                for (int c = 0; c < 16; c++) {
                    float4 vv = vr[c];
                    acc[4 * c + 0] = fmaf(pj, vv.x, acc[4 * c + 0]);
                    acc[4 * c + 1] = fmaf(pj, vv.y, acc[4 * c + 1]);
                    acc[4 * c + 2] = fmaf(pj, vv.z, acc[4 * c + 2]);
                    acc[4 * c + 3] = fmaf(pj, vv.w, acc[4 * c + 3]);
                }
            }
        }
    }

    float inv = 1.0f / l;
    // write ctx row-major [b, s, e]: b = bh>>4, head = bh&15
    float* dst = g_ctx + ((size_t)(bh >> 4) * S + qpos) * E + (bh & 15) * D;
    #pragma unroll
    for (int c = 0; c < 16; c++) {
        float4 o4;
        o4.x = acc[4 * c + 0] * inv;
        o4.y = acc[4 * c + 1] * inv;
        o4.z = acc[4 * c + 2] * inv;
        o4.w = acc[4 * c + 3] * inv;
        *(float4*)(dst + 4 * c) = o4;
    }
}

// ---------------------------------------------------------------------------
extern "C" void kernel_launch(void* const* d_in, const int* in_sizes, int n_in,
                              void* d_out, int out_size)
{
    const float* x  = (const float*)d_in[0];
    const float* Wq = (const float*)d_in[1];
    const float* bq = (const float*)d_in[2];
    const float* Wk = (const float*)d_in[3];
    const float* bk = (const float*)d_in[4];
    const float* Wv = (const float*)d_in[5];
    const float* bv = (const float*)d_in[6];
    const float* Wo = (const float*)d_in[7];
    const float* bo = (const float*)d_in[8];
    float* out = (float*)d_out;

    float *q, *k, *v, *ctx;
    cudaGetSymbolAddress((void**)&q,   g_q);
    cudaGetSymbolAddress((void**)&k,   g_k);
    cudaGetSymbolAddress((void**)&v,   g_v);
    cudaGetSymbolAddress((void**)&ctx, g_ctx);

    dim3 gblk(256);
    dim3 ggrid(E / 128, M_ROWS / 128);   // (8, 64)

    sgemm_nt<<<ggrid, gblk>>>(x, Wq, bq, q, M_ROWS, E, E, 1);
    sgemm_nt<<<ggrid, gblk>>>(x, Wk, bk, k, M_ROWS, E, E, 1);
    sgemm_nt<<<ggrid, gblk>>>(x, Wv, bv, v, M_ROWS, E, E, 1);

    const int NP = B * H * S * (D / 2);          // 4,194,304 pairs
    rope_kernel<<<(NP + 255) / 256, 256>>>(q, 0.125f);  // 1/sqrt(64)
    rope_kernel<<<(NP + 255) / 256, 256>>>(k, 1.0f);

    attn_kernel<<<dim3(S / 128, B * H), 128>>>();

    sgemm_nt<<<ggrid, gblk>>>(ctx, Wo, bo, out, M_ROWS, E, E, 0);
}

// round 2
// speedup vs baseline: 1.6919x; 1.6919x over previous
#include <cuda_runtime.h>
#include <cuda_bf16.h>
#include <math.h>
#include <stdint.h>

// Problem constants
#define B     2
#define S     4096
#define E     1024
#define H     16
#define D     64
#define WIN   256
#define M_ROWS (B * S)        // 8192

// Scratch buffers
__device__ float g_q[B * H * S * D];    // [b,h,s,d]
__device__ float g_k[B * H * S * D];
__device__ float g_v[B * H * S * D];
__device__ float g_ctx[B * S * E];      // [b,s,e]

// ---------------------------------------------------------------------------
// tf32 tensor-core GEMM:  C[n,o] = sum_k A[n,k]*Wt[o,k] + bias[o]
// A: [M,K] row-major fp32; Wt: [N,K] row-major fp32 (computes A @ Wt^T).
// mode 0: C row-major [M,N]
// mode 1: scatter to [b,h,s,d] + fused head-rope, multiply by `scale`
// mode 2: scatter to [b,h,s,d] only (V path)
// Block tile 128x128x32; 256 threads (8 warps, 2m x 4n, warp tile 64x32);
// mma.sync.aligned.m16n8k8.row.col.f32.tf32.tf32.f32
// ---------------------------------------------------------------------------
#define BM 128
#define BN 128
#define BK 32
#define SSTR (BK + 4)   // 36: makes fragment LDS conflict-free (4g+tig covers banks)

__device__ __forceinline__ uint32_t f2tf32(float x) {
    uint32_t r;
    asm("cvt.rna.tf32.f32 %0, %1;" : "=r"(r) : "f"(x));
    return r;
}

__device__ __forceinline__ void mma_tf32(float d[4], const uint32_t a[4], const uint32_t b[2]) {
    asm volatile(
        "mma.sync.aligned.m16n8k8.row.col.f32.tf32.tf32.f32 "
        "{%0,%1,%2,%3}, {%4,%5,%6,%7}, {%8,%9}, {%0,%1,%2,%3};"
        : "+f"(d[0]), "+f"(d[1]), "+f"(d[2]), "+f"(d[3])
        : "r"(a[0]), "r"(a[1]), "r"(a[2]), "r"(a[3]), "r"(b[0]), "r"(b[1]));
}

__global__ void __launch_bounds__(256)
tf32_gemm(const float* __restrict__ A, const float* __restrict__ Wt,
          const float* __restrict__ bias, float* __restrict__ C,
          int M, int N, int K, int mode, float scale)
{
    __shared__ uint32_t As[BM][SSTR];
    __shared__ uint32_t Bs[BN][SSTR];

    const int tid  = threadIdx.x;
    const int warp = tid >> 5;
    const int lane = tid & 31;
    const int g    = lane >> 2;     // group (0..7)
    const int tig  = lane & 3;      // thread-in-group
    const int wm   = warp & 1;      // 2 m-warps, 64 rows each
    const int wn   = warp >> 1;     // 4 n-warps, 32 cols each

    const int m0 = blockIdx.y * BM;
    const int n0 = blockIdx.x * BN;

    // global loading: 256 threads cover 128 rows x 32 cols; 2 threads/row, 16 floats each
    const int lrow  = tid >> 1;          // 0..127
    const int lcol  = (tid & 1) * 16;    // 0 or 16

    float acc[4][4][4];
    #pragma unroll
    for (int mi = 0; mi < 4; mi++)
        #pragma unroll
        for (int ni = 0; ni < 4; ni++)
            #pragma unroll
            for (int r = 0; r < 4; r++) acc[mi][ni][r] = 0.f;

    const float* Arow = A  + (size_t)(m0 + lrow) * K + lcol;
    const float* Brow = Wt + (size_t)(n0 + lrow) * K + lcol;

    for (int k0 = 0; k0 < K; k0 += BK) {
        __syncthreads();
        #pragma unroll
        for (int j = 0; j < 4; j++) {
            float4 a4 = *(const float4*)(Arow + k0 + 4 * j);
            float4 b4 = *(const float4*)(Brow + k0 + 4 * j);
            uint4 at = make_uint4(f2tf32(a4.x), f2tf32(a4.y), f2tf32(a4.z), f2tf32(a4.w));
            uint4 bt = make_uint4(f2tf32(b4.x), f2tf32(b4.y), f2tf32(b4.z), f2tf32(b4.w));
            *(uint4*)&As[lrow][lcol + 4 * j] = at;
            *(uint4*)&Bs[lrow][lcol + 4 * j] = bt;
        }
        __syncthreads();

        #pragma unroll
        for (int ks = 0; ks < 4; ks++) {
            const int kb = ks * 8;
            uint32_t af[4][4];
            #pragma unroll
            for (int mi = 0; mi < 4; mi++) {
                int rm = wm * 64 + mi * 16;
                af[mi][0] = As[rm + g][kb + tig];
                af[mi][1] = As[rm + g + 8][kb + tig];
                af[mi][2] = As[rm + g][kb + tig + 4];
                af[mi][3] = As[rm + g + 8][kb + tig + 4];
            }
            uint32_t bf[4][2];
            #pragma unroll
            for (int ni = 0; ni < 4; ni++) {
                int cb = wn * 32 + ni * 8;
                bf[ni][0] = Bs[cb + g][kb + tig];
                bf[ni][1] = Bs[cb + g][kb + tig + 4];
            }
            #pragma unroll
            for (int mi = 0; mi < 4; mi++)
                #pragma unroll
                for (int ni = 0; ni < 4; ni++)
                    mma_tf32(acc[mi][ni], af[mi], bf[ni]);
        }
    }

    // ---------------- epilogue ----------------
    const float Lc = 13.287712379549449f / 32.0f;  // log2(10000)/32
    #pragma unroll
    for (int mi = 0; mi < 4; mi++) {
        #pragma unroll
        for (int ni = 0; ni < 4; ni++) {
            int c0 = n0 + wn * 32 + ni * 8 + 2 * tig;   // even column
            float bias0 = bias[c0];
            float bias1 = bias[c0 + 1];
            #pragma unroll
            for (int rr = 0; rr < 2; rr++) {
                int n = m0 + wm * 64 + mi * 16 + g + rr * 8;
                float x0 = acc[mi][ni][2 * rr + 0] + bias0;
                float x1 = acc[mi][ni][2 * rr + 1] + bias1;
                float o0, o1;
                if (mode == 1) {
                    int hh = c0 >> 6;
                    int mm0 = c0 & 31;
                    int mm1 = (c0 + 1) & 31;
                    float f0 = exp2f(-(float)mm0 * Lc);
                    float f1 = exp2f(-(float)mm1 * Lc);
                    float s0, cs0, s1, cs1;
                    sincosf((float)hh * f0, &s0, &cs0);
                    sincosf((float)hh * f1, &s1, &cs1);
                    o0 = (x0 * cs0 - x1 * s0) * scale;
                    o1 = (x1 * cs1 + x0 * s1) * scale;
                } else {
                    o0 = x0;
                    o1 = x1;
                }
                if (mode == 0) {
                    *(float2*)&C[(size_t)n * N + c0] = make_float2(o0, o1);
                } else {
                    int bb = n >> 12;
                    int sr = n & 4095;
                    int hh = c0 >> 6;
                    int dd = c0 & 63;
                    float* dst = C + ((size_t)((bb << 4) + hh) * 4096 + sr) * 64 + dd;
                    *(float2*)dst = make_float2(o0, o1);
                }
            }
        }
    }
}

// ---------------------------------------------------------------------------
// Sliding-window attention, flash-style online softmax (unchanged from R0).
// ---------------------------------------------------------------------------
__global__ void __launch_bounds__(128)
attn_kernel()
{
    __shared__ float Ks[64][64];
    __shared__ float Vs[64][64];

    const int qb  = blockIdx.x;
    const int bh  = blockIdx.y;
    const int t   = threadIdx.x;
    const int qpos = qb * 128 + t;

    const float* qbase = g_q + (size_t)bh * S * D;
    const float* kbase = g_k + (size_t)bh * S * D;
    const float* vbase = g_v + (size_t)bh * S * D;

    float q[64];
    {
        const float4* qp = (const float4*)(qbase + (size_t)qpos * D);
        #pragma unroll
        for (int c = 0; c < 16; c++) {
            float4 v4 = qp[c];
            q[4 * c + 0] = v4.x; q[4 * c + 1] = v4.y;
            q[4 * c + 2] = v4.z; q[4 * c + 3] = v4.w;
        }
    }

    float acc[64];
    #pragma unroll
    for (int c = 0; c < 64; c++) acc[c] = 0.f;
    float m = -3.0e38f, l = 0.f;

    const int lrow = t >> 1;
    const int lhalf = (t & 1) * 8;

    int k0 = qb * 128 - 256;

    for (int kt = 0; kt < 10; kt++, k0 += 64) {
        __syncthreads();
        {
            int kr = k0 + lrow;
            bool ok = (kr >= 0) && (kr < S);
            const float4* kp = (const float4*)(kbase + (size_t)(ok ? kr : 0) * D);
            const float4* vp = (const float4*)(vbase + (size_t)(ok ? kr : 0) * D);
            float4 z4 = make_float4(0.f, 0.f, 0.f, 0.f);
            #pragma unroll
            for (int c = 0; c < 8; c++) {
                float4 kv = ok ? kp[lhalf + c] : z4;
                float4 vv = ok ? vp[lhalf + c] : z4;
                *(float4*)&Ks[lrow][(lhalf + c) * 4] = kv;
                *(float4*)&Vs[lrow][(lhalf + c) * 4] = vv;
            }
        }
        __syncthreads();

        for (int jb = 0; jb < 64; jb += 8) {
            float sc[8];
            #pragma unroll
            for (int jj = 0; jj < 8; jj++) {
                int j = jb + jj;
                const float4* kr4 = (const float4*)Ks[j];
                float s = 0.f;
                #pragma unroll
                for (int c = 0; c < 16; c++) {
                    float4 kv = kr4[c];
                    s = fmaf(q[4 * c + 0], kv.x, s);
                    s = fmaf(q[4 * c + 1], kv.y, s);
                    s = fmaf(q[4 * c + 2], kv.z, s);
                    s = fmaf(q[4 * c + 3], kv.w, s);
                }
                int kp = k0 + j;
                int dlt = kp - qpos;
                bool valid = (dlt >= -WIN) && (dlt <= WIN) && (kp >= 0) && (kp < S);
                sc[jj] = valid ? s : -3.0e38f;
            }
            float bm = sc[0];
            #pragma unroll
            for (int jj = 1; jj < 8; jj++) bm = fmaxf(bm, sc[jj]);
            if (bm < -1.0e37f) continue;

            float mnew  = fmaxf(m, bm);
            float scl = __expf(m - mnew);
            float p[8];
            float ps = 0.f;
            #pragma unroll
            for (int jj = 0; jj < 8; jj++) {
                p[jj] = (sc[jj] > -1.0e37f) ? __expf(sc[jj] - mnew) : 0.f;
                ps += p[jj];
            }
            l = l * scl + ps;
            m = mnew;
            #pragma unroll
            for (int c = 0; c < 64; c++) acc[c] *= scl;
            #pragma unroll
            for (int jj = 0; jj < 8; jj++) {
                float pj = p[jj];
                const float4* vr = (const float4*)Vs[jb + jj];
                #pragma unroll
                for (int c = 0; c < 16; c++) {
                    float4 vv = vr[c];
                    acc[4 * c + 0] = fmaf(pj, vv.x, acc[4 * c + 0]);
                    acc[4 * c + 1] = fmaf(pj, vv.y, acc[4 * c + 1]);
                    acc[4 * c + 2] = fmaf(pj, vv.z, acc[4 * c + 2]);
                    acc[4 * c + 3] = fmaf(pj, vv.w, acc[4 * c + 3]);
                }
            }
        }
    }

    float inv = 1.0f / l;
    float* dst = g_ctx + ((size_t)(bh >> 4) * S + qpos) * E + (bh & 15) * D;
    #pragma unroll
    for (int c = 0; c < 16; c++) {
        float4 o4;
        o4.x = acc[4 * c + 0] * inv;
        o4.y = acc[4 * c + 1] * inv;
        o4.z = acc[4 * c + 2] * inv;
        o4.w = acc[4 * c + 3] * inv;
        *(float4*)(dst + 4 * c) = o4;
    }
}

// ---------------------------------------------------------------------------
extern "C" void kernel_launch(void* const* d_in, const int* in_sizes, int n_in,
                              void* d_out, int out_size)
{
    const float* x  = (const float*)d_in[0];
    const float* Wq = (const float*)d_in[1];
    const float* bq = (const float*)d_in[2];
    const float* Wk = (const float*)d_in[3];
    const float* bk = (const float*)d_in[4];
    const float* Wv = (const float*)d_in[5];
    const float* bv = (const float*)d_in[6];
    const float* Wo = (const float*)d_in[7];
    const float* bo = (const float*)d_in[8];
    float* out = (float*)d_out;

    float *q, *k, *v, *ctx;
    cudaGetSymbolAddress((void**)&q,   g_q);
    cudaGetSymbolAddress((void**)&k,   g_k);
    cudaGetSymbolAddress((void**)&v,   g_v);
    cudaGetSymbolAddress((void**)&ctx, g_ctx);

    dim3 gblk(256);
    dim3 ggrid(E / BN, M_ROWS / BM);   // (8, 64)

    tf32_gemm<<<ggrid, gblk>>>(x, Wq, bq, q, M_ROWS, E, E, 1, 0.125f); // Q: rope+scale
    tf32_gemm<<<ggrid, gblk>>>(x, Wk, bk, k, M_ROWS, E, E, 1, 1.0f);   // K: rope
    tf32_gemm<<<ggrid, gblk>>>(x, Wv, bv, v, M_ROWS, E, E, 2, 1.0f);   // V: scatter only

    attn_kernel<<<dim3(S / 128, B * H), 128>>>();

    tf32_gemm<<<ggrid, gblk>>>(ctx, Wo, bo, out, M_ROWS, E, E, 0, 1.0f);
}

// round 4
// speedup vs baseline: 2.7593x; 1.6310x over previous
#include <cuda_runtime.h>
#include <cuda_bf16.h>
#include <math.h>
#include <stdint.h>

// Problem constants
#define B     2
#define S     4096
#define E     1024
#define H     16
#define D     64
#define WIN   256
#define M_ROWS (B * S)        // 8192

// Scratch buffers
__device__ float g_q[B * H * S * D];    // [b,h,s,d]
__device__ float g_k[B * H * S * D];
__device__ float g_v[B * H * S * D];
__device__ float g_ctx[B * S * E];      // [b,s,e]

__device__ __forceinline__ uint32_t f2tf32(float x) {
    uint32_t r;
    asm("cvt.rna.tf32.f32 %0, %1;" : "=r"(r) : "f"(x));
    return r;
}

__device__ __forceinline__ void mma_tf32(float d[4], const uint32_t a[4], const uint32_t b[2]) {
    asm volatile(
        "mma.sync.aligned.m16n8k8.row.col.f32.tf32.tf32.f32 "
        "{%0,%1,%2,%3}, {%4,%5,%6,%7}, {%8,%9}, {%0,%1,%2,%3};"
        : "+f"(d[0]), "+f"(d[1]), "+f"(d[2]), "+f"(d[3])
        : "r"(a[0]), "r"(a[1]), "r"(a[2]), "r"(a[3]), "r"(b[0]), "r"(b[1]));
}

// ---------------------------------------------------------------------------
// tf32 tensor-core GEMM (unchanged from R1):  C = A @ Wt^T + bias
// ---------------------------------------------------------------------------
#define BM 128
#define BN 128
#define BK 32
#define SSTR (BK + 4)

__global__ void __launch_bounds__(256)
tf32_gemm(const float* __restrict__ A, const float* __restrict__ Wt,
          const float* __restrict__ bias, float* __restrict__ C,
          int M, int N, int K, int mode, float scale)
{
    __shared__ uint32_t As[BM][SSTR];
    __shared__ uint32_t Bs[BN][SSTR];

    const int tid  = threadIdx.x;
    const int warp = tid >> 5;
    const int lane = tid & 31;
    const int g    = lane >> 2;
    const int tig  = lane & 3;
    const int wm   = warp & 1;
    const int wn   = warp >> 1;

    const int m0 = blockIdx.y * BM;
    const int n0 = blockIdx.x * BN;

    const int lrow  = tid >> 1;
    const int lcol  = (tid & 1) * 16;

    float acc[4][4][4];
    #pragma unroll
    for (int mi = 0; mi < 4; mi++)
        #pragma unroll
        for (int ni = 0; ni < 4; ni++)
            #pragma unroll
            for (int r = 0; r < 4; r++) acc[mi][ni][r] = 0.f;

    const float* Arow = A  + (size_t)(m0 + lrow) * K + lcol;
    const float* Brow = Wt + (size_t)(n0 + lrow) * K + lcol;

    for (int k0 = 0; k0 < K; k0 += BK) {
        __syncthreads();
        #pragma unroll
        for (int j = 0; j < 4; j++) {
            float4 a4 = *(const float4*)(Arow + k0 + 4 * j);
            float4 b4 = *(const float4*)(Brow + k0 + 4 * j);
            uint4 at = make_uint4(f2tf32(a4.x), f2tf32(a4.y), f2tf32(a4.z), f2tf32(a4.w));
            uint4 bt = make_uint4(f2tf32(b4.x), f2tf32(b4.y), f2tf32(b4.z), f2tf32(b4.w));
            *(uint4*)&As[lrow][lcol + 4 * j] = at;
            *(uint4*)&Bs[lrow][lcol + 4 * j] = bt;
        }
        __syncthreads();

        #pragma unroll
        for (int ks = 0; ks < 4; ks++) {
            const int kb = ks * 8;
            uint32_t af[4][4];
            #pragma unroll
            for (int mi = 0; mi < 4; mi++) {
                int rm = wm * 64 + mi * 16;
                af[mi][0] = As[rm + g][kb + tig];
                af[mi][1] = As[rm + g + 8][kb + tig];
                af[mi][2] = As[rm + g][kb + tig + 4];
                af[mi][3] = As[rm + g + 8][kb + tig + 4];
            }
            uint32_t bf[4][2];
            #pragma unroll
            for (int ni = 0; ni < 4; ni++) {
                int cb = wn * 32 + ni * 8;
                bf[ni][0] = Bs[cb + g][kb + tig];
                bf[ni][1] = Bs[cb + g][kb + tig + 4];
            }
            #pragma unroll
            for (int mi = 0; mi < 4; mi++)
                #pragma unroll
                for (int ni = 0; ni < 4; ni++)
                    mma_tf32(acc[mi][ni], af[mi], bf[ni]);
        }
    }

    const float Lc = 13.287712379549449f / 32.0f;  // log2(10000)/32
    #pragma unroll
    for (int mi = 0; mi < 4; mi++) {
        #pragma unroll
        for (int ni = 0; ni < 4; ni++) {
            int c0 = n0 + wn * 32 + ni * 8 + 2 * tig;
            float bias0 = bias[c0];
            float bias1 = bias[c0 + 1];
            #pragma unroll
            for (int rr = 0; rr < 2; rr++) {
                int n = m0 + wm * 64 + mi * 16 + g + rr * 8;
                float x0 = acc[mi][ni][2 * rr + 0] + bias0;
                float x1 = acc[mi][ni][2 * rr + 1] + bias1;
                float o0, o1;
                if (mode == 1) {
                    int hh = c0 >> 6;
                    int mm0 = c0 & 31;
                    int mm1 = (c0 + 1) & 31;
                    float f0 = exp2f(-(float)mm0 * Lc);
                    float f1 = exp2f(-(float)mm1 * Lc);
                    float s0, cs0, s1, cs1;
                    sincosf((float)hh * f0, &s0, &cs0);
                    sincosf((float)hh * f1, &s1, &cs1);
                    o0 = (x0 * cs0 - x1 * s0) * scale;
                    o1 = (x1 * cs1 + x0 * s1) * scale;
                } else {
                    o0 = x0;
                    o1 = x1;
                }
                if (mode == 0) {
                    *(float2*)&C[(size_t)n * N + c0] = make_float2(o0, o1);
                } else {
                    int bb = n >> 12;
                    int sr = n & 4095;
                    int hh = c0 >> 6;
                    int dd = c0 & 63;
                    float* dst = C + ((size_t)((bb << 4) + hh) * 4096 + sr) * 64 + dd;
                    *(float2*)dst = make_float2(o0, o1);
                }
            }
        }
    }
}

// ---------------------------------------------------------------------------
// Flash attention with tf32 MMA.
// Block: 64 queries, 4 warps (16 q-rows each). 18 key-tiles of 32.
// smem (u32 units): Ks [32][68], Vs(T) [64][36], Ps [64][36]; Q staged at 0.
// ---------------------------------------------------------------------------
#define KS_OFF 0
#define VS_OFF 2176          // 32*68
#define PS_OFF 4480          // +64*36
#define SM_U32 6784          // +64*36

__global__ void __launch_bounds__(128)
attn_mma()
{
    __shared__ uint32_t sm[SM_U32];

    const int t    = threadIdx.x;
    const int lane = t & 31;
    const int warp = t >> 5;
    const int g    = lane >> 2;
    const int tig  = lane & 3;
    const int qb   = blockIdx.x;
    const int bh   = blockIdx.y;
    const int q0   = qb * 64;

    const float* qg = g_q + (size_t)bh * S * D;
    const float* kg = g_k + (size_t)bh * S * D;
    const float* vg = g_v + (size_t)bh * S * D;

    // ---- stage Q (tf32) into smem, pull fragments into registers ----
    {
        uint32_t* Qs = sm;              // [64][68]
        int row  = t >> 1;
        int half = (t & 1) * 32;
        const float4* src = (const float4*)(qg + (size_t)(q0 + row) * D + half);
        #pragma unroll
        for (int i = 0; i < 8; i++) {
            float4 v4 = src[i];
            uint32_t* d = &Qs[row * 68 + half + 4 * i];
            d[0] = f2tf32(v4.x); d[1] = f2tf32(v4.y);
            d[2] = f2tf32(v4.z); d[3] = f2tf32(v4.w);
        }
    }
    __syncthreads();
    uint32_t qf[8][4];
    {
        const uint32_t* Qs = sm;
        int r0 = (warp * 16 + g) * 68;
        int r1 = r0 + 8 * 68;
        #pragma unroll
        for (int ks = 0; ks < 8; ks++) {
            int c = ks * 8 + tig;
            qf[ks][0] = Qs[r0 + c];
            qf[ks][1] = Qs[r1 + c];
            qf[ks][2] = Qs[r0 + c + 4];
            qf[ks][3] = Qs[r1 + c + 4];
        }
    }
    __syncthreads();

    uint32_t* Ks = sm + KS_OFF;   // [32 key][68]  (d-cols, tf32)
    uint32_t* Vs = sm + VS_OFF;   // [64 d][36]    (key-cols, transposed, tf32)
    uint32_t* Ps = sm + PS_OFF;   // [64 q][36]    (key-cols, tf32)

    float ctx[8][4];
    #pragma unroll
    for (int nf = 0; nf < 8; nf++)
        #pragma unroll
        for (int c = 0; c < 4; c++) ctx[nf][c] = 0.f;
    float m0r = -3.0e38f, m1r = -3.0e38f;
    float l0r = 0.f, l1r = 0.f;

    const int qp0 = q0 + warp * 16 + g;    // abs qpos of row0 (row1 = +8)

    int kbase = q0 - 256;
    for (int kt = 0; kt < 18; kt++, kbase += 32) {
        // ---- load K tile + transposed V tile (tf32 at store) ----
        {
            int lr = t >> 2;              // key row 0..31
            int lc = (t & 3) * 16;        // d col
            int kr = kbase + lr;
            bool ok = (kr >= 0) && (kr < S);
            const float4* kp = (const float4*)(kg + (size_t)(ok ? kr : 0) * D + lc);
            const float4* vp = (const float4*)(vg + (size_t)(ok ? kr : 0) * D + lc);
            float4 z4 = make_float4(0.f, 0.f, 0.f, 0.f);
            #pragma unroll
            for (int i = 0; i < 4; i++) {
                float4 kv = ok ? kp[i] : z4;
                float4 vv = ok ? vp[i] : z4;
                uint32_t* kd = &Ks[lr * 68 + lc + 4 * i];
                kd[0] = f2tf32(kv.x); kd[1] = f2tf32(kv.y);
                kd[2] = f2tf32(kv.z); kd[3] = f2tf32(kv.w);
                int d0 = lc + 4 * i;
                Vs[(d0 + 0) * 36 + lr] = f2tf32(vv.x);
                Vs[(d0 + 1) * 36 + lr] = f2tf32(vv.y);
                Vs[(d0 + 2) * 36 + lr] = f2tf32(vv.z);
                Vs[(d0 + 3) * 36 + lr] = f2tf32(vv.w);
            }
        }
        __syncthreads();

        // ---- QK^T: S[16 q x 32 k] per warp ----
        float sc[4][4];
        #pragma unroll
        for (int nf = 0; nf < 4; nf++)
            #pragma unroll
            for (int c = 0; c < 4; c++) sc[nf][c] = 0.f;

        #pragma unroll
        for (int ks = 0; ks < 8; ks++) {
            uint32_t bf[4][2];
            #pragma unroll
            for (int nf = 0; nf < 4; nf++) {
                int r = (nf * 8 + g) * 68 + ks * 8 + tig;
                bf[nf][0] = Ks[r];
                bf[nf][1] = Ks[r + 4];
            }
            #pragma unroll
            for (int nf = 0; nf < 4; nf++)
                mma_tf32(sc[nf], qf[ks], bf[nf]);
        }

        // ---- mask + online softmax ----
        float mx0 = -3.0e38f, mx1 = -3.0e38f;
        #pragma unroll
        for (int nf = 0; nf < 4; nf++) {
            int kp0 = kbase + nf * 8 + 2 * tig;
            #pragma unroll
            for (int c = 0; c < 4; c++) {
                int kpos = kp0 + (c & 1);
                int qpos = qp0 + (c >> 1) * 8;
                int dlt  = kpos - qpos;
                bool valid = (dlt >= -WIN) && (dlt <= WIN) && (kpos >= 0) && (kpos < S);
                if (!valid) sc[nf][c] = -3.0e38f;
            }
            mx0 = fmaxf(mx0, fmaxf(sc[nf][0], sc[nf][1]));
            mx1 = fmaxf(mx1, fmaxf(sc[nf][2], sc[nf][3]));
        }
        mx0 = fmaxf(mx0, __shfl_xor_sync(0xffffffffu, mx0, 1));
        mx0 = fmaxf(mx0, __shfl_xor_sync(0xffffffffu, mx0, 2));
        mx1 = fmaxf(mx1, __shfl_xor_sync(0xffffffffu, mx1, 1));
        mx1 = fmaxf(mx1, __shfl_xor_sync(0xffffffffu, mx1, 2));

        float mn0 = fmaxf(fmaxf(m0r, mx0), -1.0e30f);
        float mn1 = fmaxf(fmaxf(m1r, mx1), -1.0e30f);
        float sc0 = __expf(m0r - mn0);
        float sc1 = __expf(m1r - mn1);
        m0r = mn0; m1r = mn1;

        float rs0 = 0.f, rs1 = 0.f;
        const int prb = (warp * 16 + g) * 36;
        #pragma unroll
        for (int nf = 0; nf < 4; nf++) {
            float p0 = __expf(sc[nf][0] - mn0);
            float p1 = __expf(sc[nf][1] - mn0);
            float p2 = __expf(sc[nf][2] - mn1);
            float p3 = __expf(sc[nf][3] - mn1);
            rs0 += p0 + p1;
            rs1 += p2 + p3;
            int cofs = nf * 8 + 2 * tig;
            *(uint2*)&Ps[prb + cofs]          = make_uint2(f2tf32(p0), f2tf32(p1));
            *(uint2*)&Ps[prb + 8 * 36 + cofs] = make_uint2(f2tf32(p2), f2tf32(p3));
        }
        rs0 += __shfl_xor_sync(0xffffffffu, rs0, 1);
        rs0 += __shfl_xor_sync(0xffffffffu, rs0, 2);
        rs1 += __shfl_xor_sync(0xffffffffu, rs1, 1);
        rs1 += __shfl_xor_sync(0xffffffffu, rs1, 2);
        l0r = l0r * sc0 + rs0;
        l1r = l1r * sc1 + rs1;

        #pragma unroll
        for (int nf = 0; nf < 8; nf++) {
            ctx[nf][0] *= sc0; ctx[nf][1] *= sc0;
            ctx[nf][2] *= sc1; ctx[nf][3] *= sc1;
        }
        __syncwarp();

        // ---- PV: ctx[16 q x 64 d] += P[16 x 32] * V[32 x 64] ----
        #pragma unroll
        for (int ks = 0; ks < 4; ks++) {
            uint32_t af[4];
            int pr = prb + ks * 8 + tig;
            af[0] = Ps[pr];
            af[1] = Ps[pr + 8 * 36];
            af[2] = Ps[pr + 4];
            af[3] = Ps[pr + 8 * 36 + 4];
            #pragma unroll
            for (int nf = 0; nf < 8; nf++) {
                int vr = (nf * 8 + g) * 36 + ks * 8 + tig;
                uint32_t bf[2] = { Vs[vr], Vs[vr + 4] };
                mma_tf32(ctx[nf], af, bf);
            }
        }
        __syncthreads();
    }

    // ---- epilogue ----
    float inv0 = 1.0f / l0r;
    float inv1 = 1.0f / l1r;
    float* dst0 = g_ctx + ((size_t)(bh >> 4) * S + qp0) * E + (bh & 15) * D;
    float* dst1 = dst0 + (size_t)8 * E;
    #pragma unroll
    for (int nf = 0; nf < 8; nf++) {
        int c = nf * 8 + 2 * tig;
        *(float2*)&dst0[c] = make_float2(ctx[nf][0] * inv0, ctx[nf][1] * inv0);
        *(float2*)&dst1[c] = make_float2(ctx[nf][2] * inv1, ctx[nf][3] * inv1);
    }
}

// ---------------------------------------------------------------------------
extern "C" void kernel_launch(void* const* d_in, const int* in_sizes, int n_in,
                              void* d_out, int out_size)
{
    const float* x  = (const float*)d_in[0];
    const float* Wq = (const float*)d_in[1];
    const float* bq = (const float*)d_in[2];
    const float* Wk = (const float*)d_in[3];
    const float* bk = (const float*)d_in[4];
    const float* Wv = (const float*)d_in[5];
    const float* bv = (const float*)d_in[6];
    const float* Wo = (const float*)d_in[7];
    const float* bo = (const float*)d_in[8];
    float* out = (float*)d_out;

    float *q, *k, *v, *ctx;
    cudaGetSymbolAddress((void**)&q,   g_q);
    cudaGetSymbolAddress((void**)&k,   g_k);
    cudaGetSymbolAddress((void**)&v,   g_v);
    cudaGetSymbolAddress((void**)&ctx, g_ctx);

    dim3 gblk(256);
    dim3 ggrid(E / BN, M_ROWS / BM);

    tf32_gemm<<<ggrid, gblk>>>(x, Wq, bq, q, M_ROWS, E, E, 1, 0.125f);
    tf32_gemm<<<ggrid, gblk>>>(x, Wk, bk, k, M_ROWS, E, E, 1, 1.0f);
    tf32_gemm<<<ggrid, gblk>>>(x, Wv, bv, v, M_ROWS, E, E, 2, 1.0f);

    attn_mma<<<dim3(S / 64, B * H), 128>>>();

    tf32_gemm<<<ggrid, gblk>>>(ctx, Wo, bo, out, M_ROWS, E, E, 0, 1.0f);
}

// round 6
// speedup vs baseline: 2.8062x; 1.0170x over previous
#include <cuda_runtime.h>
#include <cuda_bf16.h>
#include <math.h>
#include <stdint.h>

// Problem constants
#define B     2
#define S     4096
#define E     1024
#define H     16
#define D     64
#define WIN   256
#define M_ROWS (B * S)        // 8192

// Scratch buffers
__device__ float g_q[B * H * S * D];    // [b,h,s,d]
__device__ float g_k[B * H * S * D];
__device__ float g_v[B * H * S * D];
__device__ float g_ctx[B * S * E];      // [b,s,e]

__device__ __forceinline__ uint32_t f2tf32(float x) {
    uint32_t r;
    asm("cvt.rna.tf32.f32 %0, %1;" : "=r"(r) : "f"(x));
    return r;
}

__device__ __forceinline__ void mma_tf32(float d[4], const uint32_t a[4], const uint32_t b[2]) {
    asm volatile(
        "mma.sync.aligned.m16n8k8.row.col.f32.tf32.tf32.f32 "
        "{%0,%1,%2,%3}, {%4,%5,%6,%7}, {%8,%9}, {%0,%1,%2,%3};"
        : "+f"(d[0]), "+f"(d[1]), "+f"(d[2]), "+f"(d[3])
        : "r"(a[0]), "r"(a[1]), "r"(a[2]), "r"(a[3]), "r"(b[0]), "r"(b[1]));
}

// ---------------------------------------------------------------------------
// tf32 tensor-core GEMM with register-prefetch pipelining:
// C = A @ Wt^T + bias ; modes as before.
// ---------------------------------------------------------------------------
#define BM 128
#define BN 128
#define BK 32
#define SSTR (BK + 4)

__global__ void __launch_bounds__(256)
tf32_gemm(const float* __restrict__ A, const float* __restrict__ Wt,
          const float* __restrict__ bias, float* __restrict__ C,
          int M, int N, int K, int mode, float scale)
{
    __shared__ uint32_t As[BM][SSTR];
    __shared__ uint32_t Bs[BN][SSTR];

    const int tid  = threadIdx.x;
    const int warp = tid >> 5;
    const int lane = tid & 31;
    const int g    = lane >> 2;
    const int tig  = lane & 3;
    const int wm   = warp & 1;
    const int wn   = warp >> 1;

    const int m0 = blockIdx.y * BM;
    const int n0 = blockIdx.x * BN;

    const int lrow  = tid >> 1;
    const int lcol  = (tid & 1) * 16;

    float acc[4][4][4];
    #pragma unroll
    for (int mi = 0; mi < 4; mi++)
        #pragma unroll
        for (int ni = 0; ni < 4; ni++)
            #pragma unroll
            for (int r = 0; r < 4; r++) acc[mi][ni][r] = 0.f;

    const float* Arow = A  + (size_t)(m0 + lrow) * K + lcol;
    const float* Brow = Wt + (size_t)(n0 + lrow) * K + lcol;

    // prefetch tile 0 into registers
    float4 pa[4], pb[4];
    #pragma unroll
    for (int j = 0; j < 4; j++) {
        pa[j] = *(const float4*)(Arow + 4 * j);
        pb[j] = *(const float4*)(Brow + 4 * j);
    }

    for (int k0 = 0; k0 < K; k0 += BK) {
        __syncthreads();
        #pragma unroll
        for (int j = 0; j < 4; j++) {
            uint4 at = make_uint4(f2tf32(pa[j].x), f2tf32(pa[j].y), f2tf32(pa[j].z), f2tf32(pa[j].w));
            uint4 bt = make_uint4(f2tf32(pb[j].x), f2tf32(pb[j].y), f2tf32(pb[j].z), f2tf32(pb[j].w));
            *(uint4*)&As[lrow][lcol + 4 * j] = at;
            *(uint4*)&Bs[lrow][lcol + 4 * j] = bt;
        }
        __syncthreads();

        // issue next tile's global loads before compute (latency hidden by MMAs)
        if (k0 + BK < K) {
            #pragma unroll
            for (int j = 0; j < 4; j++) {
                pa[j] = *(const float4*)(Arow + k0 + BK + 4 * j);
                pb[j] = *(const float4*)(Brow + k0 + BK + 4 * j);
            }
        }

        #pragma unroll
        for (int ks = 0; ks < 4; ks++) {
            const int kb = ks * 8;
            uint32_t af[4][4];
            #pragma unroll
            for (int mi = 0; mi < 4; mi++) {
                int rm = wm * 64 + mi * 16;
                af[mi][0] = As[rm + g][kb + tig];
                af[mi][1] = As[rm + g + 8][kb + tig];
                af[mi][2] = As[rm + g][kb + tig + 4];
                af[mi][3] = As[rm + g + 8][kb + tig + 4];
            }
            uint32_t bf[4][2];
            #pragma unroll
            for (int ni = 0; ni < 4; ni++) {
                int cb = wn * 32 + ni * 8;
                bf[ni][0] = Bs[cb + g][kb + tig];
                bf[ni][1] = Bs[cb + g][kb + tig + 4];
            }
            #pragma unroll
            for (int mi = 0; mi < 4; mi++)
                #pragma unroll
                for (int ni = 0; ni < 4; ni++)
                    mma_tf32(acc[mi][ni], af[mi], bf[ni]);
        }
    }

    const float Lc = 13.287712379549449f / 32.0f;  // log2(10000)/32
    #pragma unroll
    for (int mi = 0; mi < 4; mi++) {
        #pragma unroll
        for (int ni = 0; ni < 4; ni++) {
            int c0 = n0 + wn * 32 + ni * 8 + 2 * tig;
            float bias0 = bias[c0];
            float bias1 = bias[c0 + 1];
            #pragma unroll
            for (int rr = 0; rr < 2; rr++) {
                int n = m0 + wm * 64 + mi * 16 + g + rr * 8;
                float x0 = acc[mi][ni][2 * rr + 0] + bias0;
                float x1 = acc[mi][ni][2 * rr + 1] + bias1;
                float o0, o1;
                if (mode == 1) {
                    int hh = c0 >> 6;
                    int mm0 = c0 & 31;
                    int mm1 = (c0 + 1) & 31;
                    float f0 = exp2f(-(float)mm0 * Lc);
                    float f1 = exp2f(-(float)mm1 * Lc);
                    float s0, cs0, s1, cs1;
                    sincosf((float)hh * f0, &s0, &cs0);
                    sincosf((float)hh * f1, &s1, &cs1);
                    o0 = (x0 * cs0 - x1 * s0) * scale;
                    o1 = (x1 * cs1 + x0 * s1) * scale;
                } else {
                    o0 = x0;
                    o1 = x1;
                }
                if (mode == 0) {
                    *(float2*)&C[(size_t)n * N + c0] = make_float2(o0, o1);
                } else {
                    int bb = n >> 12;
                    int sr = n & 4095;
                    int hh = c0 >> 6;
                    int dd = c0 & 63;
                    float* dst = C + ((size_t)((bb << 4) + hh) * 4096 + sr) * 64 + dd;
                    *(float2*)dst = make_float2(o0, o1);
                }
            }
        }
    }
}

// ---------------------------------------------------------------------------
// Flash attention with tf32 MMA (unchanged from R4).
// ---------------------------------------------------------------------------
#define KS_OFF 0
#define VS_OFF 2176          // 32*68
#define PS_OFF 4480          // +64*36
#define SM_U32 6784          // +64*36

__global__ void __launch_bounds__(128)
attn_mma()
{
    __shared__ uint32_t sm[SM_U32];

    const int t    = threadIdx.x;
    const int lane = t & 31;
    const int warp = t >> 5;
    const int g    = lane >> 2;
    const int tig  = lane & 3;
    const int qb   = blockIdx.x;
    const int bh   = blockIdx.y;
    const int q0   = qb * 64;

    const float* qg = g_q + (size_t)bh * S * D;
    const float* kg = g_k + (size_t)bh * S * D;
    const float* vg = g_v + (size_t)bh * S * D;

    {
        uint32_t* Qs = sm;              // [64][68]
        int row  = t >> 1;
        int half = (t & 1) * 32;
        const float4* src = (const float4*)(qg + (size_t)(q0 + row) * D + half);
        #pragma unroll
        for (int i = 0; i < 8; i++) {
            float4 v4 = src[i];
            uint32_t* d = &Qs[row * 68 + half + 4 * i];
            d[0] = f2tf32(v4.x); d[1] = f2tf32(v4.y);
            d[2] = f2tf32(v4.z); d[3] = f2tf32(v4.w);
        }
    }
    __syncthreads();
    uint32_t qf[8][4];
    {
        const uint32_t* Qs = sm;
        int r0 = (warp * 16 + g) * 68;
        int r1 = r0 + 8 * 68;
        #pragma unroll
        for (int ks = 0; ks < 8; ks++) {
            int c = ks * 8 + tig;
            qf[ks][0] = Qs[r0 + c];
            qf[ks][1] = Qs[r1 + c];
            qf[ks][2] = Qs[r0 + c + 4];
            qf[ks][3] = Qs[r1 + c + 4];
        }
    }
    __syncthreads();

    uint32_t* Ks = sm + KS_OFF;   // [32 key][68]
    uint32_t* Vs = sm + VS_OFF;   // [64 d][36] (transposed)
    uint32_t* Ps = sm + PS_OFF;   // [64 q][36]

    float ctx[8][4];
    #pragma unroll
    for (int nf = 0; nf < 8; nf++)
        #pragma unroll
        for (int c = 0; c < 4; c++) ctx[nf][c] = 0.f;
    float m0r = -3.0e38f, m1r = -3.0e38f;
    float l0r = 0.f, l1r = 0.f;

    const int qp0 = q0 + warp * 16 + g;

    int kbase = q0 - 256;
    for (int kt = 0; kt < 18; kt++, kbase += 32) {
        {
            int lr = t >> 2;
            int lc = (t & 3) * 16;
            int kr = kbase + lr;
            bool ok = (kr >= 0) && (kr < S);
            const float4* kp = (const float4*)(kg + (size_t)(ok ? kr : 0) * D + lc);
            const float4* vp = (const float4*)(vg + (size_t)(ok ? kr : 0) * D + lc);
            float4 z4 = make_float4(0.f, 0.f, 0.f, 0.f);
            #pragma unroll
            for (int i = 0; i < 4; i++) {
                float4 kv = ok ? kp[i] : z4;
                float4 vv = ok ? vp[i] : z4;
                uint32_t* kd = &Ks[lr * 68 + lc + 4 * i];
                kd[0] = f2tf32(kv.x); kd[1] = f2tf32(kv.y);
                kd[2] = f2tf32(kv.z); kd[3] = f2tf32(kv.w);
                int d0 = lc + 4 * i;
                Vs[(d0 + 0) * 36 + lr] = f2tf32(vv.x);
                Vs[(d0 + 1) * 36 + lr] = f2tf32(vv.y);
                Vs[(d0 + 2) * 36 + lr] = f2tf32(vv.z);
                Vs[(d0 + 3) * 36 + lr] = f2tf32(vv.w);
            }
        }
        __syncthreads();

        float sc[4][4];
        #pragma unroll
        for (int nf = 0; nf < 4; nf++)
            #pragma unroll
            for (int c = 0; c < 4; c++) sc[nf][c] = 0.f;

        #pragma unroll
        for (int ks = 0; ks < 8; ks++) {
            uint32_t bf[4][2];
            #pragma unroll
            for (int nf = 0; nf < 4; nf++) {
                int r = (nf * 8 + g) * 68 + ks * 8 + tig;
                bf[nf][0] = Ks[r];
                bf[nf][1] = Ks[r + 4];
            }
            #pragma unroll
            for (int nf = 0; nf < 4; nf++)
                mma_tf32(sc[nf], qf[ks], bf[nf]);
        }

        float mx0 = -3.0e38f, mx1 = -3.0e38f;
        #pragma unroll
        for (int nf = 0; nf < 4; nf++) {
            int kp0 = kbase + nf * 8 + 2 * tig;
            #pragma unroll
            for (int c = 0; c < 4; c++) {
                int kpos = kp0 + (c & 1);
                int qpos = qp0 + (c >> 1) * 8;
                int dlt  = kpos - qpos;
                bool valid = (dlt >= -WIN) && (dlt <= WIN) && (kpos >= 0) && (kpos < S);
                if (!valid) sc[nf][c] = -3.0e38f;
            }
            mx0 = fmaxf(mx0, fmaxf(sc[nf][0], sc[nf][1]));
            mx1 = fmaxf(mx1, fmaxf(sc[nf][2], sc[nf][3]));
        }
        mx0 = fmaxf(mx0, __shfl_xor_sync(0xffffffffu, mx0, 1));
        mx0 = fmaxf(mx0, __shfl_xor_sync(0xffffffffu, mx0, 2));
        mx1 = fmaxf(mx1, __shfl_xor_sync(0xffffffffu, mx1, 1));
        mx1 = fmaxf(mx1, __shfl_xor_sync(0xffffffffu, mx1, 2));

        float mn0 = fmaxf(fmaxf(m0r, mx0), -1.0e30f);
        float mn1 = fmaxf(fmaxf(m1r, mx1), -1.0e30f);
        float sc0 = __expf(m0r - mn0);
        float sc1 = __expf(m1r - mn1);
        m0r = mn0; m1r = mn1;

        float rs0 = 0.f, rs1 = 0.f;
        const int prb = (warp * 16 + g) * 36;
        #pragma unroll
        for (int nf = 0; nf < 4; nf++) {
            float p0 = __expf(sc[nf][0] - mn0);
            float p1 = __expf(sc[nf][1] - mn0);
            float p2 = __expf(sc[nf][2] - mn1);
            float p3 = __expf(sc[nf][3] - mn1);
            rs0 += p0 + p1;
            rs1 += p2 + p3;
            int cofs = nf * 8 + 2 * tig;
            *(uint2*)&Ps[prb + cofs]          = make_uint2(f2tf32(p0), f2tf32(p1));
            *(uint2*)&Ps[prb + 8 * 36 + cofs] = make_uint2(f2tf32(p2), f2tf32(p3));
        }
        rs0 += __shfl_xor_sync(0xffffffffu, rs0, 1);
        rs0 += __shfl_xor_sync(0xffffffffu, rs0, 2);
        rs1 += __shfl_xor_sync(0xffffffffu, rs1, 1);
        rs1 += __shfl_xor_sync(0xffffffffu, rs1, 2);
        l0r = l0r * sc0 + rs0;
        l1r = l1r * sc1 + rs1;

        #pragma unroll
        for (int nf = 0; nf < 8; nf++) {
            ctx[nf][0] *= sc0; ctx[nf][1] *= sc0;
            ctx[nf][2] *= sc1; ctx[nf][3] *= sc1;
        }
        __syncwarp();

        #pragma unroll
        for (int ks = 0; ks < 4; ks++) {
            uint32_t af[4];
            int pr = prb + ks * 8 + tig;
            af[0] = Ps[pr];
            af[1] = Ps[pr + 8 * 36];
            af[2] = Ps[pr + 4];
            af[3] = Ps[pr + 8 * 36 + 4];
            #pragma unroll
            for (int nf = 0; nf < 8; nf++) {
                int vr = (nf * 8 + g) * 36 + ks * 8 + tig;
                uint32_t bf[2] = { Vs[vr], Vs[vr + 4] };
                mma_tf32(ctx[nf], af, bf);
            }
        }
        __syncthreads();
    }

    float inv0 = 1.0f / l0r;
    float inv1 = 1.0f / l1r;
    float* dst0 = g_ctx + ((size_t)(bh >> 4) * S + qp0) * E + (bh & 15) * D;
    float* dst1 = dst0 + (size_t)8 * E;
    #pragma unroll
    for (int nf = 0; nf < 8; nf++) {
        int c = nf * 8 + 2 * tig;
        *(float2*)&dst0[c] = make_float2(ctx[nf][0] * inv0, ctx[nf][1] * inv0);
        *(float2*)&dst1[c] = make_float2(ctx[nf][2] * inv1, ctx[nf][3] * inv1);
    }
}

// ---------------------------------------------------------------------------
extern "C" void kernel_launch(void* const* d_in, const int* in_sizes, int n_in,
                              void* d_out, int out_size)
{
    const float* x  = (const float*)d_in[0];
    const float* Wq = (const float*)d_in[1];
    const float* bq = (const float*)d_in[2];
    const float* Wk = (const float*)d_in[3];
    const float* bk = (const float*)d_in[4];
    const float* Wv = (const float*)d_in[5];
    const float* bv = (const float*)d_in[6];
    const float* Wo = (const float*)d_in[7];
    const float* bo = (const float*)d_in[8];
    float* out = (float*)d_out;

    float *q, *k, *v, *ctx;
    cudaGetSymbolAddress((void**)&q,   g_q);
    cudaGetSymbolAddress((void**)&k,   g_k);
    cudaGetSymbolAddress((void**)&v,   g_v);
    cudaGetSymbolAddress((void**)&ctx, g_ctx);

    dim3 gblk(256);
    dim3 ggrid(E / BN, M_ROWS / BM);

    tf32_gemm<<<ggrid, gblk>>>(x, Wq, bq, q, M_ROWS, E, E, 1, 0.125f);
    tf32_gemm<<<ggrid, gblk>>>(x, Wk, bk, k, M_ROWS, E, E, 1, 1.0f);
    tf32_gemm<<<ggrid, gblk>>>(x, Wv, bv, v, M_ROWS, E, E, 2, 1.0f);

    attn_mma<<<dim3(S / 64, B * H), 128>>>();

    tf32_gemm<<<ggrid, gblk>>>(ctx, Wo, bo, out, M_ROWS, E, E, 0, 1.0f);
}